// round 16
// baseline (speedup 1.0000x reference)
#include <cuda_runtime.h>
#include <cuda_fp16.h>
#include <cstdint>

#define BB 16
#define CC 512
#define HWD 1024
#define NGRP 4
#define GB (BB / NGRP)   // batches per group = 4

// Device-global scratch
__device__ __half g_Wh [(size_t)HWD * HWD];
__device__ __half g_Wm [(size_t)HWD * HWD];
__device__ __half g_n1h[(size_t)BB * CC * HWD];
__device__ __half g_n1m[(size_t)BB * CC * HWD];
__device__ __half g_n2h[(size_t)BB * CC * HWD];
__device__ __half g_n2s[(size_t)BB * CC * HWD];
__device__ __half g_n2Th[(size_t)BB * HWD * CC];
__device__ __half g_n2Tm[(size_t)BB * HWD * CC];
__device__ __half g_xTh[(size_t)HWD * BB * CC];
__device__ __half g_xTm[(size_t)HWD * BB * CC];
__device__ __half g_eh [(size_t)BB * HWD * HWD];
__device__ float  g_eT [(size_t)BB * HWD * HWD];
__device__ uint32_t g_cmax[BB * HWD];
__device__ float    g_csum[BB * HWD];

// ---------------------------------------------------------------------------
__device__ __forceinline__ uint32_t smem_u32(const void* p) {
    uint32_t a;
    asm("{ .reg .u64 t; cvta.to.shared.u64 t, %1; cvt.u32.u64 %0, t; }" : "=r"(a) : "l"(p));
    return a;
}
__device__ __forceinline__ void cp16(uint32_t saddr, const void* g) {
    asm volatile("cp.async.cg.shared.global [%0], [%1], 16;" :: "r"(saddr), "l"(g));
}
__device__ __forceinline__ void cp_commit() { asm volatile("cp.async.commit_group;"); }
template <int N>
__device__ __forceinline__ void cp_wait() {
    asm volatile("cp.async.wait_group %0;" :: "n"(N));
}
__device__ __forceinline__ void ldm4(uint32_t* r, uint32_t addr) {
    asm volatile("ldmatrix.sync.aligned.m8n8.x4.shared.b16 {%0,%1,%2,%3}, [%4];"
                 : "=r"(r[0]), "=r"(r[1]), "=r"(r[2]), "=r"(r[3]) : "r"(addr));
}
// fp32-accumulator HMMA (fp16-acc form measured 2x SLOWER on sm_103a - never use)
__device__ __forceinline__ void mma16(float* d, const uint32_t* a, uint32_t b0, uint32_t b1) {
    asm volatile(
        "mma.sync.aligned.m16n8k16.row.col.f32.f16.f16.f32 "
        "{%0,%1,%2,%3}, {%4,%5,%6,%7}, {%8,%9}, {%0,%1,%2,%3};"
        : "+f"(d[0]), "+f"(d[1]), "+f"(d[2]), "+f"(d[3])
        : "r"(a[0]), "r"(a[1]), "r"(a[2]), "r"(a[3]), "r"(b0), "r"(b1));
}
__device__ __forceinline__ uint32_t enc_f(float f) {
    uint32_t u = __float_as_uint(f);
    return (u & 0x80000000u) ? ~u : (u | 0x80000000u);
}
__device__ __forceinline__ float dec_f(uint32_t e) {
    uint32_t u = (e & 0x80000000u) ? (e ^ 0x80000000u) : ~e;
    return __uint_as_float(u);
}

// ---------------------------------------------------------------------------
// Pre-split half GEMM (round-12 champion config: 256 thr, 8 warps 2m x 4n,
// fragment double-buffer pipeline, 3-stage cp.async, launch_bounds(256,2)).
// C[m][n] = sum_k A[m][k]*B[n][k].
// PLANES=2: Ah*Bh + Ah*Bm + Am*Bh (fp32 acc).  PLANES=1: Ah*Bh.
// ---------------------------------------------------------------------------
#define PLANE_B 8192u

template <int PLANES, int OUTSPLIT, int COLMAX>
__global__ __launch_bounds__(256, 2) void gemm_h(
    const __half* __restrict__ Ah, const __half* __restrict__ Am,
    const __half* __restrict__ Bh, const __half* __restrict__ Bm,
    float* __restrict__ Cf, __half* __restrict__ Ch, __half* __restrict__ Cm,
    uint32_t* __restrict__ gmax,
    int K, int lda, int ldb, int ldc,
    size_t sA, size_t sB, size_t sC, float c_scale)
{
    extern __shared__ char smc[];
    const uint32_t sbase = smem_u32(smc);
    constexpr uint32_t STAGE_B = PLANES * 2 * PLANE_B;

    const int tid = threadIdx.x;
    const int wid = tid >> 5;
    const int lane = tid & 31;
    const int warp_m = (wid & 1) * 64;
    const int warp_n = (wid >> 1) * 32;

    Ah += (size_t)blockIdx.z * sA;  Am += (size_t)blockIdx.z * sA;
    Bh += (size_t)blockIdx.z * sB;  Bm += (size_t)blockIdx.z * sB;
    const int bm = blockIdx.y * 128;
    const int bn = blockIdx.x * 128;

    const int lrow = tid >> 1;
    const int lc0 = (tid & 1) * 2;
    const int lswz = (lrow + (lrow >> 2)) & 3;
    const __half* Asrc  = Ah + (size_t)(bm + lrow) * lda;
    const __half* Amsrc = Am + (size_t)(bm + lrow) * lda;
    const __half* Bsrc  = Bh + (size_t)(bn + lrow) * ldb;
    const __half* Bmsrc = Bm + (size_t)(bn + lrow) * ldb;

    const int nk = K / 32;

    auto load_stage = [&](int kt, int s) {
        const uint32_t dst = sbase + s * STAGE_B + lrow * 64;
        #pragma unroll
        for (int c = 0; c < 2; c++) {
            const int ch = lc0 + c;
            const uint32_t d = dst + (uint32_t)((ch ^ lswz) << 4);
            const int off = kt * 32 + ch * 8;
            cp16(d, Asrc + off);
            if (PLANES == 2) cp16(d + PLANE_B, Amsrc + off);
            cp16(d + PLANES * PLANE_B, Bsrc + off);
            if (PLANES == 2) cp16(d + 3 * PLANE_B, Bmsrc + off);
        }
        cp_commit();
    };

    load_stage(0, 0);
    load_stage(1, 1);

    float acc[4][4][4];
    #pragma unroll
    for (int i = 0; i < 4; i++)
        #pragma unroll
        for (int j = 0; j < 4; j++)
            #pragma unroll
            for (int t = 0; t < 4; t++)
                acc[i][j][t] = 0.0f;

    const int l15 = lane & 15;
    const int hi = lane >> 4;
    const int fswz = (l15 + (l15 >> 2)) & 3;
    const uint32_t kc0 = (uint32_t)((hi ^ fswz) << 4);
    const uint32_t aB0 = sbase + (warp_m + l15) * 64;
    const uint32_t bB0 = sbase + PLANES * PLANE_B + (warp_n + l15) * 64;

    uint32_t Bf[2][8];
    uint32_t Bmf[2][8];
    uint32_t Af[2][8];

    auto ldB = [&](int buf, uint32_t sb, uint32_t ko) {
        ldm4(&Bf[buf][0], sb + ko);
        ldm4(&Bf[buf][4], sb + 1024 + ko);
        if (PLANES == 2) {
            ldm4(&Bmf[buf][0], sb + PLANE_B + ko);
            ldm4(&Bmf[buf][4], sb + PLANE_B + 1024 + ko);
        }
    };
    auto ldA = [&](int buf, uint32_t sa, int i, uint32_t ko) {
        ldm4(&Af[buf][0], sa + i * 1024 + ko);
        if (PLANES == 2) ldm4(&Af[buf][4], sa + PLANE_B + i * 1024 + ko);
    };
    auto doMMA = [&](int i, int ab, int bb) {
        mma16(acc[i][0], &Af[ab][0], Bf[bb][0], Bf[bb][2]);
        mma16(acc[i][1], &Af[ab][0], Bf[bb][1], Bf[bb][3]);
        mma16(acc[i][2], &Af[ab][0], Bf[bb][4], Bf[bb][6]);
        mma16(acc[i][3], &Af[ab][0], Bf[bb][5], Bf[bb][7]);
        if (PLANES == 2) {
            mma16(acc[i][0], &Af[ab][0], Bmf[bb][0], Bmf[bb][2]);
            mma16(acc[i][1], &Af[ab][0], Bmf[bb][1], Bmf[bb][3]);
            mma16(acc[i][2], &Af[ab][0], Bmf[bb][4], Bmf[bb][6]);
            mma16(acc[i][3], &Af[ab][0], Bmf[bb][5], Bmf[bb][7]);
            mma16(acc[i][0], &Af[ab][4], Bf[bb][0], Bf[bb][2]);
            mma16(acc[i][1], &Af[ab][4], Bf[bb][1], Bf[bb][3]);
            mma16(acc[i][2], &Af[ab][4], Bf[bb][4], Bf[bb][6]);
            mma16(acc[i][3], &Af[ab][4], Bf[bb][5], Bf[bb][7]);
        }
    };

    for (int kt = 0; kt < nk; kt++) {
        cp_wait<1>();
        __syncthreads();

        const uint32_t so = (uint32_t)(kt % 3) * STAGE_B;
        const uint32_t sa = aB0 + so;
        const uint32_t sb = bB0 + so;
        const uint32_t ko0 = kc0;
        const uint32_t ko1 = kc0 ^ 32;

        ldB(0, sb, ko0);
        ldA(0, sa, 0, ko0);
        ldA(1, sa, 1, ko0);  doMMA(0, 0, 0);
        ldA(0, sa, 2, ko0);  doMMA(1, 1, 0);
        ldA(1, sa, 3, ko0);  doMMA(2, 0, 0);
        if (kt + 2 < nk) load_stage(kt + 2, (kt + 2) % 3);
        ldB(1, sb, ko1);
        ldA(0, sa, 0, ko1);  doMMA(3, 1, 0);
        ldA(1, sa, 1, ko1);  doMMA(0, 0, 1);
        ldA(0, sa, 2, ko1);  doMMA(1, 1, 1);
        ldA(1, sa, 3, ko1);  doMMA(2, 0, 1);
        doMMA(3, 1, 1);
        __syncthreads();
    }

    const int fr = lane >> 2;
    const int fc = lane & 3;
    #pragma unroll
    for (int i = 0; i < 4; i++) {
        const int row0 = bm + warp_m + i * 16 + fr;
        #pragma unroll
        for (int j = 0; j < 4; j++) {
            const int col = bn + warp_n + j * 8 + fc * 2;
            #pragma unroll
            for (int half_r = 0; half_r < 2; half_r++) {
                const size_t idx = (size_t)(row0 + half_r * 8) * ldc + col;
                const float v0 = acc[i][j][half_r * 2 + 0] * c_scale;
                const float v1 = acc[i][j][half_r * 2 + 1] * c_scale;
                if (OUTSPLIT) {
                    __half2 h = __float22half2_rn(make_float2(v0, v1));
                    float2 hf = __half22float2(h);
                    __half2 mm = __float22half2_rn(make_float2(v0 - hf.x, v1 - hf.y));
                    *(__half2*)((__half*)Ch + (size_t)blockIdx.z * sC + idx) = h;
                    *(__half2*)((__half*)Cm + (size_t)blockIdx.z * sC + idx) = mm;
                } else {
                    *(float2*)(Cf + (size_t)blockIdx.z * sC + idx) = make_float2(v0, v1);
                }
            }
        }
    }

    if (COLMAX) {
        uint32_t* smax = (uint32_t*)smc;
        if (tid < 128) smax[tid] = 0u;
        __syncthreads();
        #pragma unroll
        for (int j = 0; j < 4; j++) {
            #pragma unroll
            for (int u = 0; u < 2; u++) {
                float mv = -3.0e38f;
                #pragma unroll
                for (int i = 0; i < 4; i++) {
                    mv = fmaxf(mv, acc[i][j][u]);
                    mv = fmaxf(mv, acc[i][j][2 + u]);
                }
                atomicMax(&smax[warp_n + j * 8 + fc * 2 + u], enc_f(mv));
            }
        }
        __syncthreads();
        if (tid < 128)
            atomicMax(&gmax[blockIdx.z * HWD + bn + tid], smax[tid]);
    }
}

// ---------------------------------------------------------------------------
__global__ __launch_bounds__(256) void split_all(
    const float* __restrict__ Wc, const float* __restrict__ n1,
    __half* __restrict__ Wh, __half* __restrict__ Wm,
    __half* __restrict__ n1h, __half* __restrict__ n1m)
{
    const float* src;
    __half *h, *m;
    float scale;
    size_t i;
    if (blockIdx.x < 1024) {
        src = Wc; h = Wh; m = Wm; scale = 1024.0f;
        i = ((size_t)blockIdx.x * 256 + threadIdx.x) * 4;
    } else {
        src = n1; h = n1h; m = n1m; scale = 1.0f;
        i = ((size_t)(blockIdx.x - 1024) * 256 + threadIdx.x) * 4;
    }
    float4 v = *(const float4*)(src + i);
    v.x *= scale; v.y *= scale; v.z *= scale; v.w *= scale;
    __half2 h01 = __float22half2_rn(make_float2(v.x, v.y));
    __half2 h23 = __float22half2_rn(make_float2(v.z, v.w));
    *(__half2*)(h + i) = h01;
    *(__half2*)(h + i + 2) = h23;
    float2 f01 = __half22float2(h01), f23 = __half22float2(h23);
    *(__half2*)(m + i) = __float22half2_rn(make_float2(v.x - f01.x, v.y - f01.y));
    *(__half2*)(m + i + 2) = __float22half2_rn(make_float2(v.z - f23.x, v.w - f23.y));
}

__global__ __launch_bounds__(256) void n2_prep(
    const float* __restrict__ in, __half* __restrict__ oh,
    __half* __restrict__ th, __half* __restrict__ tm,
    uint32_t* __restrict__ cmax, float* __restrict__ csum)
{
    const int tid = threadIdx.y * 32 + threadIdx.x;
    const int bid = (blockIdx.z * gridDim.y + blockIdx.y) * gridDim.x + blockIdx.x;
    const int gidx = bid * 256 + tid;
    if (gidx < BB * HWD) { cmax[gidx] = 0u; csum[gidx] = 0.0f; }

    __shared__ float t[32][33];
    const int bx = blockIdx.x * 32;
    const int by = blockIdx.y * 32;
    const float* ib = in + (size_t)blockIdx.z * CC * HWD;
    __half* hb = oh + (size_t)blockIdx.z * CC * HWD;
    __half* tb = th + (size_t)blockIdx.z * HWD * CC;
    __half* mb = tm + (size_t)blockIdx.z * HWD * CC;
    const int x = threadIdx.x, y = threadIdx.y;
    #pragma unroll
    for (int i = 0; i < 32; i += 8) {
        const float v = ib[(size_t)(by + y + i) * HWD + bx + x];
        t[y + i][x] = v;
        hb[(size_t)(by + y + i) * HWD + bx + x] = __float2half_rn(v);
    }
    __syncthreads();
    #pragma unroll
    for (int i = 0; i < 32; i += 8) {
        const float v = t[x][y + i];
        const size_t idx = (size_t)(bx + y + i) * CC + by + x;
        __half hv = __float2half_rn(v);
        tb[idx] = hv;
        mb[idx] = __float2half_rn(v - __half2float(hv));
    }
}

// per-group variants (pointers pre-offset to the group's first batch)
__global__ __launch_bounds__(256) void expnorm(
    const float* __restrict__ eT, __half* __restrict__ eh,
    const uint32_t* __restrict__ cmax, float* __restrict__ csum)
{
    const int b = blockIdx.z;   // local batch within group
    const int col = blockIdx.x * 256 + threadIdx.x;
    const int row0 = blockIdx.y * 128;
    const float cm = dec_f(cmax[b * HWD + col]);
    const float* src = eT + (size_t)b * HWD * HWD + (size_t)row0 * HWD + col;
    __half* dst = eh + (size_t)b * HWD * HWD + (size_t)row0 * HWD + col;
    float s = 0.0f;
    #pragma unroll 8
    for (int r = 0; r < 128; r++) {
        const float w = __expf(src[(size_t)r * HWD] - cm);
        s += w;
        dst[(size_t)r * HWD] = __float2half_rn(w);
    }
    atomicAdd(&csum[b * HWD + col], s);
}

__global__ __launch_bounds__(256) void scale_n2(
    const __half* __restrict__ n2h, __half* __restrict__ n2s,
    const float* __restrict__ csum)
{
    const size_t i = ((size_t)blockIdx.x * blockDim.x + threadIdx.x) * 4;
    if (i >= (size_t)GB * CC * HWD) return;
    const int b = (int)(i / ((size_t)CC * HWD));   // local batch within group
    const int k = (int)(i % HWD);
    const float* cs = csum + b * HWD + k;
    __half2 a01 = *(const __half2*)(n2h + i);
    __half2 a23 = *(const __half2*)(n2h + i + 2);
    float2 f01 = __half22float2(a01), f23 = __half22float2(a23);
    const float i0 = 1.0f / cs[0], i1 = 1.0f / cs[1];
    const float i2 = 1.0f / cs[2], i3 = 1.0f / cs[3];
    *(__half2*)(n2s + i) = __float22half2_rn(make_float2(f01.x * i0, f01.y * i1));
    *(__half2*)(n2s + i + 2) = __float22half2_rn(make_float2(f23.x * i2, f23.y * i3));
}

// ---------------------------------------------------------------------------
extern "C" void kernel_launch(void* const* d_in, const int* in_sizes, int n_in,
                              void* d_out, int out_size)
{
    const float* node1 = (const float*)d_in[0];
    const float* node2 = (const float*)d_in[1];
    const float* Wc    = (const float*)d_in[2];
    float* out = (float*)d_out;

    __half *Wh, *Wm, *n1h, *n1m, *n2h, *n2s, *n2Th, *n2Tm, *xTh, *xTm, *eh;
    float *eT, *csum;
    uint32_t* cmax;
    cudaGetSymbolAddress((void**)&Wh,   g_Wh);
    cudaGetSymbolAddress((void**)&Wm,   g_Wm);
    cudaGetSymbolAddress((void**)&n1h,  g_n1h);
    cudaGetSymbolAddress((void**)&n1m,  g_n1m);
    cudaGetSymbolAddress((void**)&n2h,  g_n2h);
    cudaGetSymbolAddress((void**)&n2s,  g_n2s);
    cudaGetSymbolAddress((void**)&n2Th, g_n2Th);
    cudaGetSymbolAddress((void**)&n2Tm, g_n2Tm);
    cudaGetSymbolAddress((void**)&xTh,  g_xTh);
    cudaGetSymbolAddress((void**)&xTm,  g_xTm);
    cudaGetSymbolAddress((void**)&eh,   g_eh);
    cudaGetSymbolAddress((void**)&eT,   g_eT);
    cudaGetSymbolAddress((void**)&cmax, g_cmax);
    cudaGetSymbolAddress((void**)&csum, g_csum);

    const int SM2 = 3 * 4 * PLANE_B;  // 96KB
    const int SM1 = 3 * 2 * PLANE_B;  // 48KB
    cudaFuncSetAttribute((const void*)gemm_h<2, 1, 0>,
                         cudaFuncAttributeMaxDynamicSharedMemorySize, SM2);
    cudaFuncSetAttribute((const void*)gemm_h<2, 0, 1>,
                         cudaFuncAttributeMaxDynamicSharedMemorySize, SM2);
    cudaFuncSetAttribute((const void*)gemm_h<1, 0, 0>,
                         cudaFuncAttributeMaxDynamicSharedMemorySize, SM1);

    static cudaStream_t s2 = 0;
    static cudaEvent_t evFork = 0, evJoin = 0, evS = 0;
    static cudaEvent_t evE[NGRP];
    if (!s2) {
        cudaStreamCreateWithFlags(&s2, cudaStreamNonBlocking);
        cudaEventCreateWithFlags(&evFork, cudaEventDisableTiming);
        cudaEventCreateWithFlags(&evJoin, cudaEventDisableTiming);
        cudaEventCreateWithFlags(&evS, cudaEventDisableTiming);
        for (int g = 0; g < NGRP; g++)
            cudaEventCreateWithFlags(&evE[g], cudaEventDisableTiming);
    }

    // fork: n2_prep (+stats init) hidden under split/GEMM1
    cudaEventRecord(evFork, 0);
    cudaStreamWaitEvent(s2, evFork, 0);
    n2_prep<<<dim3(HWD / 32, CC / 32, BB), dim3(32, 8), 0, s2>>>(
        node2, n2h, n2Th, n2Tm, cmax, csum);
    cudaEventRecord(evJoin, s2);

    split_all<<<1024 + 8192, 256>>>(Wc, node1, Wh, Wm, n1h, n1m);

    // GEMM1: xT[o][m] = sum_h Wc[o][h]*n1[m][h]; M=1024, N=8192, K=1024; split out
    gemm_h<2, 1, 0><<<dim3(8192 / 128, HWD / 128, 1), 256, SM2>>>(
        Wh, Wm, n1h, n1m, (float*)0, xTh, xTm, (uint32_t*)0,
        HWD, HWD, HWD, 8192, 0, 0, 0, 1.0f / 1024.0f);

    cudaStreamWaitEvent(0, evJoin, 0);

    // GEMM2 (monolithic): eT[b][j][o] = sum_c n2T[b][j][c]*xT[o][b*512+c]; + colmax
    gemm_h<2, 0, 1><<<dim3(HWD / 128, HWD / 128, BB), 256, SM2>>>(
        n2Th, n2Tm, xTh, xTm, eT, (__half*)0, (__half*)0, cmax,
        CC, CC, 8192, HWD,
        (size_t)HWD * CC, (size_t)CC, (size_t)HWD * HWD, 1.0f);

    // pipelined elementwise chain: expnorm(g) on stream0, scale_n2(g) on s2
    for (int g = 0; g < NGRP; g++) {
        const size_t bo = (size_t)g * GB;
        expnorm<<<dim3(HWD / 256, HWD / 128, GB), 256>>>(
            eT + bo * HWD * HWD, eh + bo * HWD * HWD,
            cmax + bo * HWD, csum + bo * HWD);
        cudaEventRecord(evE[g], 0);
        cudaStreamWaitEvent(s2, evE[g], 0);
        scale_n2<<<(int)(((size_t)GB * CC * HWD) / 1024), 256, 0, s2>>>(
            n2h + bo * CC * HWD, n2s + bo * CC * HWD, csum + bo * HWD);
    }
    cudaEventRecord(evS, s2);
    cudaStreamWaitEvent(0, evS, 0);

    // GEMM3 (monolithic): out[b][c][j] = sum_k n2s[b][c][k]*eh[b][j][k]
    gemm_h<1, 0, 0><<<dim3(HWD / 128, CC / 128, BB), 256, SM1>>>(
        n2s, n2s, eh, eh, out, (__half*)0, (__half*)0, (uint32_t*)0,
        HWD, HWD, HWD, HWD,
        (size_t)CC * HWD, (size_t)HWD * HWD, (size_t)CC * HWD, 1.0f);
}

// round 17
// speedup vs baseline: 1.0831x; 1.0831x over previous
#include <cuda_runtime.h>
#include <cuda_fp16.h>
#include <cstdint>

#define BB 16
#define CC 512
#define HWD 1024

// Device-global scratch
__device__ __half g_Wh [(size_t)HWD * HWD];
__device__ __half g_Wm [(size_t)HWD * HWD];
__device__ __half g_n1h[(size_t)BB * CC * HWD];
__device__ __half g_n1m[(size_t)BB * CC * HWD];
__device__ __half g_n2h[(size_t)BB * CC * HWD];
__device__ __half g_n2s[(size_t)BB * CC * HWD];
__device__ __half g_n2Th[(size_t)BB * HWD * CC];
__device__ __half g_n2Tm[(size_t)BB * HWD * CC];
__device__ __half g_xTh[(size_t)HWD * BB * CC];
__device__ __half g_xTm[(size_t)HWD * BB * CC];
__device__ __half g_eh [(size_t)BB * HWD * HWD];
__device__ float  g_eT [(size_t)BB * HWD * HWD];
__device__ uint32_t g_cmax[BB * HWD];
__device__ float    g_csum[BB * HWD];

// ---------------------------------------------------------------------------
__device__ __forceinline__ uint32_t smem_u32(const void* p) {
    uint32_t a;
    asm("{ .reg .u64 t; cvta.to.shared.u64 t, %1; cvt.u32.u64 %0, t; }" : "=r"(a) : "l"(p));
    return a;
}
__device__ __forceinline__ void cp16(uint32_t saddr, const void* g) {
    asm volatile("cp.async.cg.shared.global [%0], [%1], 16;" :: "r"(saddr), "l"(g));
}
__device__ __forceinline__ void cp_commit() { asm volatile("cp.async.commit_group;"); }
template <int N>
__device__ __forceinline__ void cp_wait() {
    asm volatile("cp.async.wait_group %0;" :: "n"(N));
}
__device__ __forceinline__ void ldm4(uint32_t* r, uint32_t addr) {
    asm volatile("ldmatrix.sync.aligned.m8n8.x4.shared.b16 {%0,%1,%2,%3}, [%4];"
                 : "=r"(r[0]), "=r"(r[1]), "=r"(r[2]), "=r"(r[3]) : "r"(addr));
}
// fp32-accumulator HMMA. NOT volatile: register-only op, lets ptxas schedule
// the full kt-body DAG instead of my program order. (fp16-acc form measured
// 2x SLOWER on sm_103a - never use.)
__device__ __forceinline__ void mma16(float* d, const uint32_t* a, uint32_t b0, uint32_t b1) {
    asm("mma.sync.aligned.m16n8k16.row.col.f32.f16.f16.f32 "
        "{%0,%1,%2,%3}, {%4,%5,%6,%7}, {%8,%9}, {%0,%1,%2,%3};"
        : "+f"(d[0]), "+f"(d[1]), "+f"(d[2]), "+f"(d[3])
        : "r"(a[0]), "r"(a[1]), "r"(a[2]), "r"(a[3]), "r"(b0), "r"(b1));
}
__device__ __forceinline__ uint32_t enc_f(float f) {
    uint32_t u = __float_as_uint(f);
    return (u & 0x80000000u) ? ~u : (u | 0x80000000u);
}
__device__ __forceinline__ float dec_f(uint32_t e) {
    uint32_t u = (e & 0x80000000u) ? (e ^ 0x80000000u) : ~e;
    return __uint_as_float(u);
}

// ---------------------------------------------------------------------------
// Pre-split half GEMM (round-12 champion config: 256 thr, 8 warps 2m x 4n,
// fragment double-buffer pipeline, 3-stage cp.async, launch_bounds(256,2)).
// C[m][n] = sum_k A[m][k]*B[n][k].
// PLANES=2: Ah*Bh + Ah*Bm + Am*Bh (fp32 acc).  PLANES=1: Ah*Bh.
// ---------------------------------------------------------------------------
#define PLANE_B 8192u

template <int PLANES, int OUTSPLIT, int COLMAX>
__global__ __launch_bounds__(256, 2) void gemm_h(
    const __half* __restrict__ Ah, const __half* __restrict__ Am,
    const __half* __restrict__ Bh, const __half* __restrict__ Bm,
    float* __restrict__ Cf, __half* __restrict__ Ch, __half* __restrict__ Cm,
    uint32_t* __restrict__ gmax,
    int K, int lda, int ldb, int ldc,
    size_t sA, size_t sB, size_t sC, float c_scale)
{
    extern __shared__ char smc[];
    const uint32_t sbase = smem_u32(smc);
    constexpr uint32_t STAGE_B = PLANES * 2 * PLANE_B;

    const int tid = threadIdx.x;
    const int wid = tid >> 5;
    const int lane = tid & 31;
    const int warp_m = (wid & 1) * 64;
    const int warp_n = (wid >> 1) * 32;

    Ah += (size_t)blockIdx.z * sA;  Am += (size_t)blockIdx.z * sA;
    Bh += (size_t)blockIdx.z * sB;  Bm += (size_t)blockIdx.z * sB;
    const int bm = blockIdx.y * 128;
    const int bn = blockIdx.x * 128;

    const int lrow = tid >> 1;
    const int lc0 = (tid & 1) * 2;
    const int lswz = (lrow + (lrow >> 2)) & 3;
    const __half* Asrc  = Ah + (size_t)(bm + lrow) * lda;
    const __half* Amsrc = Am + (size_t)(bm + lrow) * lda;
    const __half* Bsrc  = Bh + (size_t)(bn + lrow) * ldb;
    const __half* Bmsrc = Bm + (size_t)(bn + lrow) * ldb;

    const int nk = K / 32;

    auto load_stage = [&](int kt, int s) {
        const uint32_t dst = sbase + s * STAGE_B + lrow * 64;
        #pragma unroll
        for (int c = 0; c < 2; c++) {
            const int ch = lc0 + c;
            const uint32_t d = dst + (uint32_t)((ch ^ lswz) << 4);
            const int off = kt * 32 + ch * 8;
            cp16(d, Asrc + off);
            if (PLANES == 2) cp16(d + PLANE_B, Amsrc + off);
            cp16(d + PLANES * PLANE_B, Bsrc + off);
            if (PLANES == 2) cp16(d + 3 * PLANE_B, Bmsrc + off);
        }
        cp_commit();
    };

    load_stage(0, 0);
    load_stage(1, 1);

    float acc[4][4][4];
    #pragma unroll
    for (int i = 0; i < 4; i++)
        #pragma unroll
        for (int j = 0; j < 4; j++)
            #pragma unroll
            for (int t = 0; t < 4; t++)
                acc[i][j][t] = 0.0f;

    const int l15 = lane & 15;
    const int hi = lane >> 4;
    const int fswz = (l15 + (l15 >> 2)) & 3;
    const uint32_t kc0 = (uint32_t)((hi ^ fswz) << 4);
    const uint32_t aB0 = sbase + (warp_m + l15) * 64;
    const uint32_t bB0 = sbase + PLANES * PLANE_B + (warp_n + l15) * 64;

    uint32_t Bf[2][8];
    uint32_t Bmf[2][8];
    uint32_t Af[2][8];

    auto ldB = [&](int buf, uint32_t sb, uint32_t ko) {
        ldm4(&Bf[buf][0], sb + ko);
        ldm4(&Bf[buf][4], sb + 1024 + ko);
        if (PLANES == 2) {
            ldm4(&Bmf[buf][0], sb + PLANE_B + ko);
            ldm4(&Bmf[buf][4], sb + PLANE_B + 1024 + ko);
        }
    };
    auto ldA = [&](int buf, uint32_t sa, int i, uint32_t ko) {
        ldm4(&Af[buf][0], sa + i * 1024 + ko);
        if (PLANES == 2) ldm4(&Af[buf][4], sa + PLANE_B + i * 1024 + ko);
    };
    auto doMMA = [&](int i, int ab, int bb) {
        mma16(acc[i][0], &Af[ab][0], Bf[bb][0], Bf[bb][2]);
        mma16(acc[i][1], &Af[ab][0], Bf[bb][1], Bf[bb][3]);
        mma16(acc[i][2], &Af[ab][0], Bf[bb][4], Bf[bb][6]);
        mma16(acc[i][3], &Af[ab][0], Bf[bb][5], Bf[bb][7]);
        if (PLANES == 2) {
            mma16(acc[i][0], &Af[ab][0], Bmf[bb][0], Bmf[bb][2]);
            mma16(acc[i][1], &Af[ab][0], Bmf[bb][1], Bmf[bb][3]);
            mma16(acc[i][2], &Af[ab][0], Bmf[bb][4], Bmf[bb][6]);
            mma16(acc[i][3], &Af[ab][0], Bmf[bb][5], Bmf[bb][7]);
            mma16(acc[i][0], &Af[ab][4], Bf[bb][0], Bf[bb][2]);
            mma16(acc[i][1], &Af[ab][4], Bf[bb][1], Bf[bb][3]);
            mma16(acc[i][2], &Af[ab][4], Bf[bb][4], Bf[bb][6]);
            mma16(acc[i][3], &Af[ab][4], Bf[bb][5], Bf[bb][7]);
        }
    };

    for (int kt = 0; kt < nk; kt++) {
        cp_wait<1>();
        __syncthreads();

        const uint32_t so = (uint32_t)(kt % 3) * STAGE_B;
        const uint32_t sa = aB0 + so;
        const uint32_t sb = bB0 + so;
        const uint32_t ko0 = kc0;
        const uint32_t ko1 = kc0 ^ 32;

        ldB(0, sb, ko0);
        ldA(0, sa, 0, ko0);
        ldA(1, sa, 1, ko0);  doMMA(0, 0, 0);
        ldA(0, sa, 2, ko0);  doMMA(1, 1, 0);
        ldA(1, sa, 3, ko0);  doMMA(2, 0, 0);
        if (kt + 2 < nk) load_stage(kt + 2, (kt + 2) % 3);
        ldB(1, sb, ko1);
        ldA(0, sa, 0, ko1);  doMMA(3, 1, 0);
        ldA(1, sa, 1, ko1);  doMMA(0, 0, 1);
        ldA(0, sa, 2, ko1);  doMMA(1, 1, 1);
        ldA(1, sa, 3, ko1);  doMMA(2, 0, 1);
        doMMA(3, 1, 1);
        __syncthreads();
    }

    const int fr = lane >> 2;
    const int fc = lane & 3;
    #pragma unroll
    for (int i = 0; i < 4; i++) {
        const int row0 = bm + warp_m + i * 16 + fr;
        #pragma unroll
        for (int j = 0; j < 4; j++) {
            const int col = bn + warp_n + j * 8 + fc * 2;
            #pragma unroll
            for (int half_r = 0; half_r < 2; half_r++) {
                const size_t idx = (size_t)(row0 + half_r * 8) * ldc + col;
                const float v0 = acc[i][j][half_r * 2 + 0] * c_scale;
                const float v1 = acc[i][j][half_r * 2 + 1] * c_scale;
                if (OUTSPLIT) {
                    __half2 h = __float22half2_rn(make_float2(v0, v1));
                    float2 hf = __half22float2(h);
                    __half2 mm = __float22half2_rn(make_float2(v0 - hf.x, v1 - hf.y));
                    *(__half2*)((__half*)Ch + (size_t)blockIdx.z * sC + idx) = h;
                    *(__half2*)((__half*)Cm + (size_t)blockIdx.z * sC + idx) = mm;
                } else {
                    *(float2*)(Cf + (size_t)blockIdx.z * sC + idx) = make_float2(v0, v1);
                }
            }
        }
    }

    if (COLMAX) {
        uint32_t* smax = (uint32_t*)smc;
        if (tid < 128) smax[tid] = 0u;
        __syncthreads();
        #pragma unroll
        for (int j = 0; j < 4; j++) {
            #pragma unroll
            for (int u = 0; u < 2; u++) {
                float mv = -3.0e38f;
                #pragma unroll
                for (int i = 0; i < 4; i++) {
                    mv = fmaxf(mv, acc[i][j][u]);
                    mv = fmaxf(mv, acc[i][j][2 + u]);
                }
                atomicMax(&smax[warp_n + j * 8 + fc * 2 + u], enc_f(mv));
            }
        }
        __syncthreads();
        if (tid < 128)
            atomicMax(&gmax[blockIdx.z * HWD + bn + tid], smax[tid]);
    }
}

// ---------------------------------------------------------------------------
__global__ __launch_bounds__(256) void split_all(
    const float* __restrict__ Wc, const float* __restrict__ n1,
    __half* __restrict__ Wh, __half* __restrict__ Wm,
    __half* __restrict__ n1h, __half* __restrict__ n1m)
{
    const float* src;
    __half *h, *m;
    float scale;
    size_t i;
    if (blockIdx.x < 1024) {
        src = Wc; h = Wh; m = Wm; scale = 1024.0f;
        i = ((size_t)blockIdx.x * 256 + threadIdx.x) * 4;
    } else {
        src = n1; h = n1h; m = n1m; scale = 1.0f;
        i = ((size_t)(blockIdx.x - 1024) * 256 + threadIdx.x) * 4;
    }
    float4 v = *(const float4*)(src + i);
    v.x *= scale; v.y *= scale; v.z *= scale; v.w *= scale;
    __half2 h01 = __float22half2_rn(make_float2(v.x, v.y));
    __half2 h23 = __float22half2_rn(make_float2(v.z, v.w));
    *(__half2*)(h + i) = h01;
    *(__half2*)(h + i + 2) = h23;
    float2 f01 = __half22float2(h01), f23 = __half22float2(h23);
    *(__half2*)(m + i) = __float22half2_rn(make_float2(v.x - f01.x, v.y - f01.y));
    *(__half2*)(m + i + 2) = __float22half2_rn(make_float2(v.z - f23.x, v.w - f23.y));
}

__global__ __launch_bounds__(256) void n2_prep(
    const float* __restrict__ in, __half* __restrict__ oh,
    __half* __restrict__ th, __half* __restrict__ tm,
    uint32_t* __restrict__ cmax, float* __restrict__ csum)
{
    const int tid = threadIdx.y * 32 + threadIdx.x;
    const int bid = (blockIdx.z * gridDim.y + blockIdx.y) * gridDim.x + blockIdx.x;
    const int gidx = bid * 256 + tid;
    if (gidx < BB * HWD) { cmax[gidx] = 0u; csum[gidx] = 0.0f; }

    __shared__ float t[32][33];
    const int bx = blockIdx.x * 32;
    const int by = blockIdx.y * 32;
    const float* ib = in + (size_t)blockIdx.z * CC * HWD;
    __half* hb = oh + (size_t)blockIdx.z * CC * HWD;
    __half* tb = th + (size_t)blockIdx.z * HWD * CC;
    __half* mb = tm + (size_t)blockIdx.z * HWD * CC;
    const int x = threadIdx.x, y = threadIdx.y;
    #pragma unroll
    for (int i = 0; i < 32; i += 8) {
        const float v = ib[(size_t)(by + y + i) * HWD + bx + x];
        t[y + i][x] = v;
        hb[(size_t)(by + y + i) * HWD + bx + x] = __float2half_rn(v);
    }
    __syncthreads();
    #pragma unroll
    for (int i = 0; i < 32; i += 8) {
        const float v = t[x][y + i];
        const size_t idx = (size_t)(bx + y + i) * CC + by + x;
        __half hv = __float2half_rn(v);
        tb[idx] = hv;
        mb[idx] = __float2half_rn(v - __half2float(hv));
    }
}

__global__ __launch_bounds__(256) void expnorm(
    const float* __restrict__ eT, __half* __restrict__ eh,
    const uint32_t* __restrict__ cmax, float* __restrict__ csum)
{
    const int b = blockIdx.z;
    const int col = blockIdx.x * 256 + threadIdx.x;
    const int row0 = blockIdx.y * 128;
    const float cm = dec_f(cmax[b * HWD + col]);
    const float* src = eT + (size_t)b * HWD * HWD + (size_t)row0 * HWD + col;
    __half* dst = eh + (size_t)b * HWD * HWD + (size_t)row0 * HWD + col;
    float s = 0.0f;
    #pragma unroll 8
    for (int r = 0; r < 128; r++) {
        const float w = __expf(src[(size_t)r * HWD] - cm);
        s += w;
        dst[(size_t)r * HWD] = __float2half_rn(w);
    }
    atomicAdd(&csum[b * HWD + col], s);
}

__global__ __launch_bounds__(256) void scale_n2(
    const __half* __restrict__ n2h, __half* __restrict__ n2s,
    const float* __restrict__ csum)
{
    const size_t i = ((size_t)blockIdx.x * blockDim.x + threadIdx.x) * 4;
    if (i >= (size_t)BB * CC * HWD) return;
    const int b = (int)(i / ((size_t)CC * HWD));
    const int k = (int)(i % HWD);
    const float* cs = csum + b * HWD + k;
    __half2 a01 = *(const __half2*)(n2h + i);
    __half2 a23 = *(const __half2*)(n2h + i + 2);
    float2 f01 = __half22float2(a01), f23 = __half22float2(a23);
    const float i0 = 1.0f / cs[0], i1 = 1.0f / cs[1];
    const float i2 = 1.0f / cs[2], i3 = 1.0f / cs[3];
    *(__half2*)(n2s + i) = __float22half2_rn(make_float2(f01.x * i0, f01.y * i1));
    *(__half2*)(n2s + i + 2) = __float22half2_rn(make_float2(f23.x * i2, f23.y * i3));
}

// ---------------------------------------------------------------------------
extern "C" void kernel_launch(void* const* d_in, const int* in_sizes, int n_in,
                              void* d_out, int out_size)
{
    const float* node1 = (const float*)d_in[0];
    const float* node2 = (const float*)d_in[1];
    const float* Wc    = (const float*)d_in[2];
    float* out = (float*)d_out;

    __half *Wh, *Wm, *n1h, *n1m, *n2h, *n2s, *n2Th, *n2Tm, *xTh, *xTm, *eh;
    float *eT, *csum;
    uint32_t* cmax;
    cudaGetSymbolAddress((void**)&Wh,   g_Wh);
    cudaGetSymbolAddress((void**)&Wm,   g_Wm);
    cudaGetSymbolAddress((void**)&n1h,  g_n1h);
    cudaGetSymbolAddress((void**)&n1m,  g_n1m);
    cudaGetSymbolAddress((void**)&n2h,  g_n2h);
    cudaGetSymbolAddress((void**)&n2s,  g_n2s);
    cudaGetSymbolAddress((void**)&n2Th, g_n2Th);
    cudaGetSymbolAddress((void**)&n2Tm, g_n2Tm);
    cudaGetSymbolAddress((void**)&xTh,  g_xTh);
    cudaGetSymbolAddress((void**)&xTm,  g_xTm);
    cudaGetSymbolAddress((void**)&eh,   g_eh);
    cudaGetSymbolAddress((void**)&eT,   g_eT);
    cudaGetSymbolAddress((void**)&cmax, g_cmax);
    cudaGetSymbolAddress((void**)&csum, g_csum);

    const int SM2 = 3 * 4 * PLANE_B;  // 96KB
    const int SM1 = 3 * 2 * PLANE_B;  // 48KB
    cudaFuncSetAttribute((const void*)gemm_h<2, 1, 0>,
                         cudaFuncAttributeMaxDynamicSharedMemorySize, SM2);
    cudaFuncSetAttribute((const void*)gemm_h<2, 0, 1>,
                         cudaFuncAttributeMaxDynamicSharedMemorySize, SM2);
    cudaFuncSetAttribute((const void*)gemm_h<1, 0, 0>,
                         cudaFuncAttributeMaxDynamicSharedMemorySize, SM1);

    static cudaStream_t s2 = 0;
    static cudaEvent_t evFork = 0, evJoin = 0;
    if (!s2) {
        cudaStreamCreateWithFlags(&s2, cudaStreamNonBlocking);
        cudaEventCreateWithFlags(&evFork, cudaEventDisableTiming);
        cudaEventCreateWithFlags(&evJoin, cudaEventDisableTiming);
    }

    // fork: n2_prep (+stats init) on side stream, hidden under split/GEMM1
    cudaEventRecord(evFork, 0);
    cudaStreamWaitEvent(s2, evFork, 0);
    n2_prep<<<dim3(HWD / 32, CC / 32, BB), dim3(32, 8), 0, s2>>>(
        node2, n2h, n2Th, n2Tm, cmax, csum);
    cudaEventRecord(evJoin, s2);

    split_all<<<1024 + 8192, 256>>>(Wc, node1, Wh, Wm, n1h, n1m);

    // GEMM1: xT[o][m] = sum_h Wc[o][h]*n1[m][h]; split output
    gemm_h<2, 1, 0><<<dim3(8192 / 128, HWD / 128, 1), 256, SM2>>>(
        Wh, Wm, n1h, n1m, (float*)0, xTh, xTm, (uint32_t*)0,
        HWD, HWD, HWD, 8192, 0, 0, 0, 1.0f / 1024.0f);

    cudaStreamWaitEvent(0, evJoin, 0);

    // GEMM2 (swapped): eT[b][j][o] = sum_c n2T[b][j][c]*xT[o][b*512+c]; + colmax
    gemm_h<2, 0, 1><<<dim3(HWD / 128, HWD / 128, BB), 256, SM2>>>(
        n2Th, n2Tm, xTh, xTm, eT, (__half*)0, (__half*)0, cmax,
        CC, CC, 8192, HWD,
        (size_t)HWD * CC, (size_t)CC, (size_t)HWD * HWD, 1.0f);

    expnorm<<<dim3(HWD / 256, HWD / 128, BB), 256>>>(eT, eh, cmax, csum);

    scale_n2<<<(int)(((size_t)BB * CC * HWD) / 1024), 256>>>(n2h, n2s, csum);

    // GEMM3: out[b][c][j] = sum_k n2s[b][c][k]*eh[b][j][k]
    gemm_h<1, 0, 0><<<dim3(HWD / 128, CC / 128, BB), 256, SM1>>>(
        n2s, n2s, eh, eh, out, (__half*)0, (__half*)0, (uint32_t*)0,
        HWD, HWD, HWD, HWD,
        (size_t)CC * HWD, (size_t)HWD * HWD, (size_t)CC * HWD, 1.0f);
}